// round 16
// baseline (speedup 1.0000x reference)
#include <cuda_runtime.h>
#include <cuda_fp16.h>
#include <cstddef>
#include <cstdint>

// ---------------------------------------------------------------------------
// GNN: relu(x@W_in+b); 2x SAGEConv(mean) + BN(eval) + relu; out GEMM.
// N=100000, E=1.6M, D_IN=256, H=128, D_OUT=64, fp32 in/out.
//
// R15: each SAGE layer split into self-GEMM (h@Wr -> fp32 partial) overlapped
// with the gather on a second stream, then neighbor-GEMM (mean@Wl) whose
// epilogue adds the partial (+bias/BN/relu). Same math as the fused dual GEMM.
// CSR-overlap fork/join kept from R14.
// ---------------------------------------------------------------------------

#define MAX_N 100000
#define MAX_E 1600000
#define HID   128

__device__ __half g_h16a[(size_t)MAX_N * HID];
__device__ __half g_h16b[(size_t)MAX_N * HID];
__device__ __half g_h16c[(size_t)MAX_N * HID];
__device__ __half g_g16 [(size_t)MAX_N * HID];
__device__ float  g_P   [(size_t)MAX_N * HID];    // self-GEMM partial
__device__ int    g_degi  [MAX_N];
__device__ int    g_cursor[MAX_N];
__device__ int    g_rowptr[MAX_N + 1];
__device__ int    g_csr   [MAX_E];
__device__ int    g_bsum  [1024];
__device__ __half g_wt[128 * 256 + 4 * 128 * 128 + 64 * 128];  // all weights fp16

// segment offsets in g_wt
#define WT_IN   0
#define WT_L1   (128 * 256)
#define WT_R1   (WT_L1 + 128 * 128)
#define WT_L2   (WT_R1 + 128 * 128)
#define WT_R2   (WT_L2 + 128 * 128)
#define WT_OUT  (WT_R2 + 128 * 128)
#define WT_TOT  (WT_OUT + 64 * 128)

// ---------------------------------------------------------------------------
// helpers
// ---------------------------------------------------------------------------
__device__ __forceinline__ uint32_t smem_u32(const void* p) {
    uint32_t a;
    asm("{ .reg .u64 t; cvta.to.shared.u64 t, %1; cvt.u32.u64 %0, t; }"
        : "=r"(a) : "l"(p));
    return a;
}

__device__ __forceinline__ void ldsm_x4(uint32_t* r, uint32_t addr) {
    asm volatile("ldmatrix.sync.aligned.m8n8.x4.shared.b16 {%0,%1,%2,%3}, [%4];"
                 : "=r"(r[0]), "=r"(r[1]), "=r"(r[2]), "=r"(r[3]) : "r"(addr));
}

__device__ __forceinline__ void mma_f16(float* c, const uint32_t* a, const uint32_t* b) {
    asm volatile("mma.sync.aligned.m16n8k16.row.col.f32.f16.f16.f32 "
                 "{%0,%1,%2,%3}, {%4,%5,%6,%7}, {%8,%9}, {%0,%1,%2,%3};"
                 : "+f"(c[0]), "+f"(c[1]), "+f"(c[2]), "+f"(c[3])
                 : "r"(a[0]), "r"(a[1]), "r"(a[2]), "r"(a[3]),
                   "r"(b[0]), "r"(b[1]));
}

__device__ __forceinline__ void cp16(uint32_t saddr, const void* gptr) {
    asm volatile("cp.async.ca.shared.global [%0], [%1], 16;"
                 :: "r"(saddr), "l"(gptr) : "memory");
}
__device__ __forceinline__ void cp16z(uint32_t saddr, const void* gptr, bool valid) {
    int sz = valid ? 16 : 0;
    asm volatile("cp.async.ca.shared.global [%0], [%1], 16, %2;"
                 :: "r"(saddr), "l"(gptr), "r"(sz) : "memory");
}
__device__ __forceinline__ void cp_commit() {
    asm volatile("cp.async.commit_group;" ::: "memory");
}
template<int NN>
__device__ __forceinline__ void cp_wait() {
    asm volatile("cp.async.wait_group %0;" :: "n"(NN) : "memory");
}

__device__ __forceinline__ uint32_t packh2(float a, float b) {
    __half2 t = __floats2half2_rn(a, b);
    return *reinterpret_cast<uint32_t*>(&t);
}

// ---------------------------------------------------------------------------
// CSR build
// ---------------------------------------------------------------------------
__global__ void zero_int_kernel(int* __restrict__ a, int* __restrict__ b, int n) {
    int i = blockIdx.x * blockDim.x + threadIdx.x;
    if (i < n) { a[i] = 0; b[i] = 0; }
}

__global__ void degi_kernel(const int* __restrict__ dst, int* __restrict__ deg, int E) {
    int e = blockIdx.x * blockDim.x + threadIdx.x;
    if (e < E) atomicAdd(&deg[dst[e]], 1);
}

__global__ void scan1_kernel(const int* __restrict__ deg, int* __restrict__ rowptr,
                             int* __restrict__ bsum, int n) {
    __shared__ int warp_tot[8];
    int t = threadIdx.x, lane = t & 31, wid = t >> 5;
    int base = blockIdx.x * 1024 + t * 4;
    int v0 = (base + 0 < n) ? deg[base + 0] : 0;
    int v1 = (base + 1 < n) ? deg[base + 1] : 0;
    int v2 = (base + 2 < n) ? deg[base + 2] : 0;
    int v3 = (base + 3 < n) ? deg[base + 3] : 0;
    int tot = v0 + v1 + v2 + v3;

    int inc = tot;
#pragma unroll
    for (int off = 1; off < 32; off <<= 1) {
        int y = __shfl_up_sync(0xFFFFFFFF, inc, off);
        if (lane >= off) inc += y;
    }
    if (lane == 31) warp_tot[wid] = inc;
    __syncthreads();
    if (wid == 0) {
        int w = (lane < 8) ? warp_tot[lane] : 0;
        int wi = w;
#pragma unroll
        for (int off = 1; off < 8; off <<= 1) {
            int y = __shfl_up_sync(0xFFFFFFFF, wi, off);
            if (lane >= off) wi += y;
        }
        if (lane < 8) warp_tot[lane] = wi - w;
    }
    __syncthreads();
    int excl = warp_tot[wid] + inc - tot;

    if (base + 0 < n) rowptr[base + 0] = excl;
    if (base + 1 < n) rowptr[base + 1] = excl + v0;
    if (base + 2 < n) rowptr[base + 2] = excl + v0 + v1;
    if (base + 3 < n) rowptr[base + 3] = excl + v0 + v1 + v2;
    if (t == 255) bsum[blockIdx.x] = warp_tot[7] + inc;
}

__global__ void scan2_kernel(int* __restrict__ bsum, int nblk) {
    __shared__ int sh[1024];
    int t = threadIdx.x;
#pragma unroll
    for (int i = 0; i < 4; ++i) {
        int idx = t + i * 256;
        sh[idx] = (idx < nblk) ? bsum[idx] : 0;
    }
    __syncthreads();
    for (int off = 1; off < 1024; off <<= 1) {
        int v[4];
#pragma unroll
        for (int i = 0; i < 4; ++i) {
            int idx = t + i * 256;
            v[i] = (idx >= off) ? sh[idx - off] : 0;
        }
        __syncthreads();
#pragma unroll
        for (int i = 0; i < 4; ++i) sh[t + i * 256] += v[i];
        __syncthreads();
    }
#pragma unroll
    for (int i = 0; i < 4; ++i) {
        int idx = t + i * 256;
        if (idx < nblk) bsum[idx] = (idx == 0) ? 0 : sh[idx - 1];
    }
}

__global__ void scan3_kernel(int* __restrict__ rowptr, const int* __restrict__ bsum,
                             int n, int E) {
    int i = blockIdx.x * blockDim.x + threadIdx.x;
    if (i < n) rowptr[i] += bsum[i >> 10];
    if (i == 0) rowptr[n] = E;
}

__global__ void fill_kernel(const int* __restrict__ src, const int* __restrict__ dst,
                            const int* __restrict__ rowptr, int* __restrict__ cursor,
                            int* __restrict__ csr, int E) {
    int e = blockIdx.x * blockDim.x + threadIdx.x;
    if (e >= E) return;
    int d = dst[e];
    int pos = rowptr[d] + atomicAdd(&cursor[d], 1);
    csr[pos] = src[e];
}

// ---------------------------------------------------------------------------
// Gather (fp16 in -> fp16 mean out). Warp per node, 8-edge unroll.
// ---------------------------------------------------------------------------
__global__ void __launch_bounds__(256)
gather_kernel(const uint2* __restrict__ h2, const int* __restrict__ rowptr,
              const int* __restrict__ csr, __half* __restrict__ G, int n) {
    int gw   = (blockIdx.x * blockDim.x + threadIdx.x) >> 5;
    int lane = threadIdx.x & 31;
    if (gw >= n) return;
    int s0 = rowptr[gw], s1 = rowptr[gw + 1];
    float ax = 0.f, ay = 0.f, az = 0.f, aw = 0.f;
    int j = s0;
    for (; j + 8 <= s1; j += 8) {
        int idx[8];
        uint2 u[8];
#pragma unroll
        for (int q = 0; q < 8; ++q) idx[q] = __ldg(&csr[j + q]);
#pragma unroll
        for (int q = 0; q < 8; ++q) u[q] = h2[(size_t)idx[q] * 32 + lane];
#pragma unroll
        for (int q = 0; q < 8; ++q) {
            float2 p0 = __half22float2(*reinterpret_cast<__half2*>(&u[q].x));
            float2 p1 = __half22float2(*reinterpret_cast<__half2*>(&u[q].y));
            ax += p0.x; ay += p0.y; az += p1.x; aw += p1.y;
        }
    }
    for (; j + 4 <= s1; j += 4) {
        int idx[4];
        uint2 u[4];
#pragma unroll
        for (int q = 0; q < 4; ++q) idx[q] = __ldg(&csr[j + q]);
#pragma unroll
        for (int q = 0; q < 4; ++q) u[q] = h2[(size_t)idx[q] * 32 + lane];
#pragma unroll
        for (int q = 0; q < 4; ++q) {
            float2 p0 = __half22float2(*reinterpret_cast<__half2*>(&u[q].x));
            float2 p1 = __half22float2(*reinterpret_cast<__half2*>(&u[q].y));
            ax += p0.x; ay += p0.y; az += p1.x; aw += p1.y;
        }
    }
    for (; j < s1; ++j) {
        int i0 = __ldg(&csr[j]);
        uint2 u = h2[(size_t)i0 * 32 + lane];
        float2 p0 = __half22float2(*reinterpret_cast<__half2*>(&u.x));
        float2 p1 = __half22float2(*reinterpret_cast<__half2*>(&u.y));
        ax += p0.x; ay += p0.y; az += p1.x; aw += p1.y;
    }
    float rd = 1.0f / fmaxf((float)(s1 - s0), 1.0f);
    uint2 ov = make_uint2(packh2(ax * rd, ay * rd), packh2(az * rd, aw * rd));
    *(uint2*)(G + (size_t)gw * HID + lane * 4) = ov;
}

// ---------------------------------------------------------------------------
// Fused weight prep: all weights transposed to fp16 in one launch.
// segments: w_in[256,128] | wl1[128,128] | wr1 | wl2 | wr2 | wo[128,64]
// ---------------------------------------------------------------------------
__global__ void wprep_all_kernel(const float* __restrict__ w_in,
                                 const float* __restrict__ wl1,
                                 const float* __restrict__ wr1,
                                 const float* __restrict__ wl2,
                                 const float* __restrict__ wr2,
                                 const float* __restrict__ wo,
                                 __half* __restrict__ wt) {
    int i = blockIdx.x * blockDim.x + threadIdx.x;
    const float* W; int Ktot, BNw, j; __half* o;
    if (i < WT_L1)       { j = i;          W = w_in; Ktot = 256; BNw = 128; o = wt + WT_IN; }
    else if (i < WT_R1)  { j = i - WT_L1;  W = wl1;  Ktot = 128; BNw = 128; o = wt + WT_L1; }
    else if (i < WT_L2)  { j = i - WT_R1;  W = wr1;  Ktot = 128; BNw = 128; o = wt + WT_R1; }
    else if (i < WT_R2)  { j = i - WT_L2;  W = wl2;  Ktot = 128; BNw = 128; o = wt + WT_L2; }
    else if (i < WT_OUT) { j = i - WT_R2;  W = wr2;  Ktot = 128; BNw = 128; o = wt + WT_R2; }
    else if (i < WT_TOT) { j = i - WT_OUT; W = wo;   Ktot = 128; BNw = 64;  o = wt + WT_OUT; }
    else return;
    int n = j / Ktot, k = j % Ktot;
    o[j] = __float2half_rn(W[(size_t)k * BNw + n]);
}

// ---------------------------------------------------------------------------
// Persistent fp16 HMMA GEMM.
//  F32A: A fp32 (X) converted in reg staging; else A fp16 via cp.async.
//  RAW: write raw fp32 accum (no bias/act) to C.
//  PARTIAL: epilogue adds fp32 partial Pin before bias/BN/relu.
//  OUTF32: fp32 C out; else fp16 H out.
// ---------------------------------------------------------------------------
template<int BN, int NC, bool RELU, bool AFF, bool F32A, bool OUTF32,
         bool RAW, bool PARTIAL>
__global__ void __launch_bounds__(256, 2)
mma_gemm_kernel(const float* __restrict__ X, int sX,
                const __half* __restrict__ A0, int sA0,
                const __half* __restrict__ W,
                const float* __restrict__ bias,
                const float* __restrict__ gamma,
                const float* __restrict__ beta,
                const float* __restrict__ Pin,
                float* __restrict__ C,
                __half* __restrict__ H, int Nrows, int nBlocksRow)
{
    constexpr int KTOT   = NC * 32;
    constexpr int WN     = BN / 2;
    constexpr int NT8    = WN / 8;
    constexpr int NT16   = WN / 16;
    constexpr int APITCH = 80;
    constexpr int ABYTES = 128 * APITCH;
    constexpr int BPITCH = KTOT * 2 + 16;
    constexpr int BOFF   = 3 * ABYTES;
    constexpr int K8     = KTOT / 8;

    extern __shared__ __align__(128) char smem[];
    const uint32_t sbase = smem_u32(smem);
    const uint32_t bbase = sbase + BOFF;

    const int tid  = threadIdx.x;
    const int wid  = tid >> 5;
    const int lane = tid & 31;
    const int wm   = wid & 3;
    const int wn   = wid >> 2;

    // load full B once
    for (int s = tid; s < BN * K8; s += 256) {
        int n = s / K8, k8 = s % K8;
        cp16(bbase + n * BPITCH + k8 * 16, W + (size_t)n * KTOT + k8 * 8);
    }
    cp_commit();

    const int cb = wn * WN + 2 * (lane & 3);
    float2 scv[NT8], shv[NT8];
#pragma unroll
    for (int nt = 0; nt < NT8; ++nt) {
        float s0 = 1.0f, s1 = 1.0f, h0 = 0.0f, h1 = 0.0f;
        if constexpr (!RAW) {
            int col = cb + nt * 8;
            if constexpr (AFF) {
                s0 = __ldg(&gamma[col])     * rsqrtf(1.0f + 1e-5f);
                s1 = __ldg(&gamma[col + 1]) * rsqrtf(1.0f + 1e-5f);
                h0 = s0 * __ldg(&bias[col])     + __ldg(&beta[col]);
                h1 = s1 * __ldg(&bias[col + 1]) + __ldg(&beta[col + 1]);
            } else {
                h0 = __ldg(&bias[col]);
                h1 = __ldg(&bias[col + 1]);
            }
        }
        scv[nt] = make_float2(s0, s1);
        shv[nt] = make_float2(h0, h1);
    }

    float4 af[2][2];

    auto load_tileA_f32 = [&](int row0, int c) {
#pragma unroll
        for (int s = 0; s < 2; ++s) {
            int f = tid + s * 256;
            int r = f >> 2, seg = f & 3;
            float4 v0 = make_float4(0.f, 0.f, 0.f, 0.f), v1 = v0;
            int grow = row0 + r;
            if (grow < Nrows) {
                const float* p = X + (size_t)grow * sX + c * 32 + seg * 8;
                v0 = *(const float4*)p;
                v1 = *(const float4*)(p + 4);
            }
            af[s][0] = v0; af[s][1] = v1;
        }
    };

    auto store_tileA_f16 = [&](int buf) {
        char* sp = smem + buf * ABYTES;
#pragma unroll
        for (int s = 0; s < 2; ++s) {
            int f = tid + s * 256;
            int r = f >> 2, seg = f & 3;
            uint4 v;
            v.x = packh2(af[s][0].x, af[s][0].y);
            v.y = packh2(af[s][0].z, af[s][0].w);
            v.z = packh2(af[s][1].x, af[s][1].y);
            v.w = packh2(af[s][1].z, af[s][1].w);
            *(uint4*)(sp + r * APITCH + seg * 16) = v;
        }
    };

    auto loadA_async = [&](int row0, int c, int buf) {
        const uint32_t abase = sbase + buf * ABYTES;
#pragma unroll
        for (int s = 0; s < 2; ++s) {
            int f = tid + s * 256;
            int r = f >> 2, seg = f & 3;
            int grow = row0 + r;
            bool ok = grow < Nrows;
            size_t g = (size_t)(ok ? grow : 0) * sA0 + c * 32 + seg * 8;
            cp16z(abase + r * APITCH + seg * 16, A0 + g, ok);
        }
    };

    float acc[2][NT8][4];

    auto compute = [&](int buf, int c) {
        const uint32_t aA = sbase + buf * ABYTES;
#pragma unroll
        for (int ks = 0; ks < 2; ++ks) {
            uint32_t a[2][4];
#pragma unroll
            for (int mt = 0; mt < 2; ++mt) {
                uint32_t off = (uint32_t)((wm * 32 + mt * 16 + (lane & 15)) * APITCH
                                          + (ks * 16 + (lane >> 4) * 8) * 2);
                ldsm_x4(a[mt], aA + off);
            }
#pragma unroll
            for (int nt2 = 0; nt2 < NT16; ++nt2) {
                int n_idx = wn * WN + nt2 * 16 + (lane & 7) + ((lane >> 4) & 1) * 8;
                int kg    = c * 32 + ks * 16 + ((lane >> 3) & 1) * 8;
                uint32_t b[4];
                ldsm_x4(b, bbase + (uint32_t)(n_idx * BPITCH + kg * 2));
#pragma unroll
                for (int mt = 0; mt < 2; ++mt) {
                    mma_f16(acc[mt][nt2 * 2 + 0], a[mt], b + 0);
                    mma_f16(acc[mt][nt2 * 2 + 1], a[mt], b + 2);
                }
            }
        }
    };

    for (int rb = blockIdx.x; rb < nBlocksRow; rb += gridDim.x) {
        const int row0 = rb * 128;

#pragma unroll
        for (int mt = 0; mt < 2; ++mt)
#pragma unroll
            for (int nt = 0; nt < NT8; ++nt)
#pragma unroll
                for (int q = 0; q < 4; ++q) acc[mt][nt][q] = 0.0f;

        if constexpr (!F32A) {
            loadA_async(row0, 0, 0); cp_commit();
            loadA_async(row0, 1, 1); cp_commit();
#pragma unroll
            for (int c = 0; c < NC; ++c) {
                if (c == NC - 1) cp_wait<0>(); else cp_wait<1>();
                __syncthreads();
                compute(c % 3, c);
                if (c + 2 < NC) {
                    loadA_async(row0, c + 2, (c + 2) % 3);
                    cp_commit();
                }
            }
        } else {
            cp_wait<0>();
            load_tileA_f32(row0, 0);
            store_tileA_f16(0);
            __syncthreads();
#pragma unroll
            for (int c = 0; c < NC; ++c) {
                if (c + 1 < NC) load_tileA_f32(row0, c + 1);
                compute(c & 1, c);
                if (c + 1 < NC) store_tileA_f16((c + 1) & 1);
                __syncthreads();
            }
        }

        const int rbase = row0 + wm * 32 + (lane >> 2);
#pragma unroll
        for (int mt = 0; mt < 2; ++mt) {
#pragma unroll
            for (int h = 0; h < 2; ++h) {
                int row = rbase + mt * 16 + h * 8;
                if (row >= Nrows) continue;
#pragma unroll
                for (int nt = 0; nt < NT8; ++nt) {
                    size_t base = (size_t)row * BN + cb + nt * 8;
                    float a0 = acc[mt][nt][h * 2 + 0];
                    float a1 = acc[mt][nt][h * 2 + 1];
                    if constexpr (RAW) {
                        *(float2*)(C + base) = make_float2(a0, a1);
                    } else {
                        if constexpr (PARTIAL) {
                            float2 pv = *(const float2*)(Pin + base);
                            a0 += pv.x; a1 += pv.y;
                        }
                        float v0 = a0 * scv[nt].x + shv[nt].x;
                        float v1 = a1 * scv[nt].y + shv[nt].y;
                        if constexpr (RELU) { v0 = fmaxf(v0, 0.0f); v1 = fmaxf(v1, 0.0f); }
                        if constexpr (OUTF32) {
                            *(float2*)(C + base) = make_float2(v0, v1);
                        } else {
                            *(uint32_t*)(H + base) = packh2(v0, v1);
                        }
                    }
                }
            }
        }
        __syncthreads();
    }
}

// ---------------------------------------------------------------------------
// Host launcher — overlapped schedule:
//   main: wprep, GEMM_in, self1, (wait g1) nbr1, gather2, (wait s2) nbr2, out
//   s2:   CSR chain, (wait in) gather1, (wait l1) self2
// ---------------------------------------------------------------------------
extern "C" void kernel_launch(void* const* d_in, const int* in_sizes, int n_in,
                              void* d_out, int out_size)
{
    const float* x     = (const float*)d_in[0];
    const int*   eidx  = (const int*)  d_in[1];
    const float* w_in  = (const float*)d_in[2];
    const float* b_in  = (const float*)d_in[3];
    const float* w_l1  = (const float*)d_in[4];
    const float* b_l1  = (const float*)d_in[5];
    const float* w_r1  = (const float*)d_in[6];
    const float* g1    = (const float*)d_in[7];
    const float* be1   = (const float*)d_in[8];
    const float* w_l2  = (const float*)d_in[9];
    const float* b_l2  = (const float*)d_in[10];
    const float* w_r2  = (const float*)d_in[11];
    const float* g2    = (const float*)d_in[12];
    const float* be2   = (const float*)d_in[13];
    const float* w_out = (const float*)d_in[14];
    const float* b_out = (const float*)d_in[15];
    float* out = (float*)d_out;

    const int N = in_sizes[0] / 256;
    const int E = in_sizes[1] / 2;
    const int* src = eidx;
    const int* dst = eidx + E;

    __half *h16a, *h16b, *h16c, *g16, *wt;
    float* P;
    int *degi, *cursor, *rowptr, *csr, *bsum;
    cudaGetSymbolAddress((void**)&h16a,   g_h16a);
    cudaGetSymbolAddress((void**)&h16b,   g_h16b);
    cudaGetSymbolAddress((void**)&h16c,   g_h16c);
    cudaGetSymbolAddress((void**)&g16,    g_g16);
    cudaGetSymbolAddress((void**)&P,      g_P);
    cudaGetSymbolAddress((void**)&degi,   g_degi);
    cudaGetSymbolAddress((void**)&cursor, g_cursor);
    cudaGetSymbolAddress((void**)&rowptr, g_rowptr);
    cudaGetSymbolAddress((void**)&csr,    g_csr);
    cudaGetSymbolAddress((void**)&bsum,   g_bsum);
    cudaGetSymbolAddress((void**)&wt,     g_wt);

    const int nBlocks    = (N + 255) / 256;
    const int eBlocks    = (E + 255) / 256;
    const int rowBlocks  = (N + 127) / 128;
    const int gemmGrid   = 304;
    const int scanBlocks = (N + 1023) / 1024;
    const int gatherBlocks = (int)(((long long)N * 32 + 255) / 256);

    const int S_K256      = 3 * (128 * 80) + 128 * (256 * 2 + 16);  // 98304
    const int S_K128_B128 = 3 * (128 * 80) + 128 * (128 * 2 + 16);  // 65536
    const int S_K128_B64  = 3 * (128 * 80) + 64  * (128 * 2 + 16);  // 48128

    // instantiations
    auto kIn   = mma_gemm_kernel<128, 8, true,  false, true,  false, false, false>;
    auto kSelf = mma_gemm_kernel<128, 4, false, false, false, true,  true,  false>;
    auto kNbr  = mma_gemm_kernel<128, 4, true,  true,  false, false, false, true >;
    auto kOut  = mma_gemm_kernel<64,  4, false, false, false, true,  false, false>;
    cudaFuncSetAttribute(kIn,   cudaFuncAttributeMaxDynamicSharedMemorySize, S_K256);
    cudaFuncSetAttribute(kSelf, cudaFuncAttributeMaxDynamicSharedMemorySize, S_K128_B128);
    cudaFuncSetAttribute(kNbr,  cudaFuncAttributeMaxDynamicSharedMemorySize, S_K128_B128);
    cudaFuncSetAttribute(kOut,  cudaFuncAttributeMaxDynamicSharedMemorySize, S_K128_B64);

    // lazy side-stream + events
    static cudaStream_t s2 = nullptr;
    static cudaEvent_t  eFork = nullptr, eIn = nullptr, eG1 = nullptr,
                        eL1 = nullptr, eS2 = nullptr;
    if (s2 == nullptr) {
        cudaStreamCreateWithFlags(&s2, cudaStreamNonBlocking);
        cudaEventCreateWithFlags(&eFork, cudaEventDisableTiming);
        cudaEventCreateWithFlags(&eIn,   cudaEventDisableTiming);
        cudaEventCreateWithFlags(&eG1,   cudaEventDisableTiming);
        cudaEventCreateWithFlags(&eL1,   cudaEventDisableTiming);
        cudaEventCreateWithFlags(&eS2,   cudaEventDisableTiming);
    }

    // ---- fork ----
    cudaEventRecord(eFork, 0);
    cudaStreamWaitEvent(s2, eFork, 0);

    // s2: CSR chain
    zero_int_kernel<<<nBlocks, 256, 0, s2>>>(degi, cursor, N);
    degi_kernel<<<eBlocks, 256, 0, s2>>>(dst, degi, E);
    scan1_kernel<<<scanBlocks, 256, 0, s2>>>(degi, rowptr, bsum, N);
    scan2_kernel<<<1, 256, 0, s2>>>(bsum, scanBlocks);
    scan3_kernel<<<nBlocks, 256, 0, s2>>>(rowptr, bsum, N, E);
    fill_kernel<<<eBlocks, 256, 0, s2>>>(src, dst, rowptr, cursor, csr, E);

    // main: weights + input GEMM -> h16a
    wprep_all_kernel<<<(WT_TOT + 255) / 256, 256>>>(w_in, w_l1, w_r1,
                                                    w_l2, w_r2, w_out, wt);
    kIn<<<gemmGrid, 256, S_K256>>>(
        x, 256, nullptr, 0, wt + WT_IN,
        b_in, nullptr, nullptr, nullptr, nullptr, h16a, N, rowBlocks);
    cudaEventRecord(eIn, 0);

    // s2: gather1 (after CSR in-stream; needs h16a)
    cudaStreamWaitEvent(s2, eIn, 0);
    gather_kernel<<<gatherBlocks, 256, 0, s2>>>((const uint2*)h16a, rowptr, csr,
                                                g16, N);
    cudaEventRecord(eG1, s2);

    // main: self1 = h16a @ Wr1 -> P (concurrent with gather1)
    kSelf<<<gemmGrid, 256, S_K128_B128>>>(
        nullptr, 0, h16a, 128, wt + WT_R1,
        nullptr, nullptr, nullptr, nullptr, P, nullptr, N, rowBlocks);

    // main: nbr1 = relu(bn(g16@Wl1 + P + b)) -> h16b
    cudaStreamWaitEvent(0, eG1, 0);
    kNbr<<<gemmGrid, 256, S_K128_B128>>>(
        nullptr, 0, g16, 128, wt + WT_L1,
        b_l1, g1, be1, P, nullptr, h16b, N, rowBlocks);
    cudaEventRecord(eL1, 0);

    // s2: self2 = h16b @ Wr2 -> P (concurrent with gather2)
    cudaStreamWaitEvent(s2, eL1, 0);
    kSelf<<<gemmGrid, 256, S_K128_B128, s2>>>(
        nullptr, 0, h16b, 128, wt + WT_R2,
        nullptr, nullptr, nullptr, nullptr, P, nullptr, N, rowBlocks);
    cudaEventRecord(eS2, s2);

    // main: gather2 (needs h16b)
    gather_kernel<<<gatherBlocks, 256>>>((const uint2*)h16b, rowptr, csr, g16, N);

    // main: nbr2 -> h16c
    cudaStreamWaitEvent(0, eS2, 0);
    kNbr<<<gemmGrid, 256, S_K128_B128>>>(
        nullptr, 0, g16, 128, wt + WT_L2,
        b_l2, g2, be2, P, nullptr, h16c, N, rowBlocks);

    // main: output layer
    kOut<<<gemmGrid, 256, S_K128_B64>>>(
        nullptr, 0, h16c, 128, wt + WT_OUT,
        b_out, nullptr, nullptr, nullptr, out, nullptr, N, rowBlocks);
}

// round 17
// speedup vs baseline: 1.1205x; 1.1205x over previous
#include <cuda_runtime.h>
#include <cuda_fp16.h>
#include <cstddef>
#include <cstdint>

// ---------------------------------------------------------------------------
// GNN: relu(x@W_in+b); 2x SAGEConv(mean) + BN(eval) + relu; out GEMM.
// N=100000, E=1.6M, D_IN=256, H=128, D_OUT=64, fp32 in/out.
//
// R16: REVERT R15's self/nbr split (partial-P traffic + grid contention
// regressed). Back to R14: fused dual-K GEMM + CSR fork-join overlap.
// New: weight prep split — only w_in prep on the critical path; layer/out
// weights prepped on the side stream inside the input-GEMM shadow.
// ---------------------------------------------------------------------------

#define MAX_N 100000
#define MAX_E 1600000
#define HID   128

__device__ __half g_h16a[(size_t)MAX_N * HID];
__device__ __half g_h16b[(size_t)MAX_N * HID];
__device__ __half g_h16c[(size_t)MAX_N * HID];
__device__ __half g_g16 [(size_t)MAX_N * HID];
__device__ int    g_degi  [MAX_N];
__device__ int    g_cursor[MAX_N];
__device__ int    g_rowptr[MAX_N + 1];
__device__ int    g_csr   [MAX_E];
__device__ int    g_bsum  [1024];
__device__ __half g_wt[4][128 * 256];   // transposed fp16 weights per GEMM

// ---------------------------------------------------------------------------
// helpers
// ---------------------------------------------------------------------------
__device__ __forceinline__ uint32_t smem_u32(const void* p) {
    uint32_t a;
    asm("{ .reg .u64 t; cvta.to.shared.u64 t, %1; cvt.u32.u64 %0, t; }"
        : "=r"(a) : "l"(p));
    return a;
}

__device__ __forceinline__ void ldsm_x4(uint32_t* r, uint32_t addr) {
    asm volatile("ldmatrix.sync.aligned.m8n8.x4.shared.b16 {%0,%1,%2,%3}, [%4];"
                 : "=r"(r[0]), "=r"(r[1]), "=r"(r[2]), "=r"(r[3]) : "r"(addr));
}

__device__ __forceinline__ void mma_f16(float* c, const uint32_t* a, const uint32_t* b) {
    asm volatile("mma.sync.aligned.m16n8k16.row.col.f32.f16.f16.f32 "
                 "{%0,%1,%2,%3}, {%4,%5,%6,%7}, {%8,%9}, {%0,%1,%2,%3};"
                 : "+f"(c[0]), "+f"(c[1]), "+f"(c[2]), "+f"(c[3])
                 : "r"(a[0]), "r"(a[1]), "r"(a[2]), "r"(a[3]),
                   "r"(b[0]), "r"(b[1]));
}

__device__ __forceinline__ void cp16(uint32_t saddr, const void* gptr) {
    asm volatile("cp.async.ca.shared.global [%0], [%1], 16;"
                 :: "r"(saddr), "l"(gptr) : "memory");
}
__device__ __forceinline__ void cp16z(uint32_t saddr, const void* gptr, bool valid) {
    int sz = valid ? 16 : 0;
    asm volatile("cp.async.ca.shared.global [%0], [%1], 16, %2;"
                 :: "r"(saddr), "l"(gptr), "r"(sz) : "memory");
}
__device__ __forceinline__ void cp_commit() {
    asm volatile("cp.async.commit_group;" ::: "memory");
}
template<int NN>
__device__ __forceinline__ void cp_wait() {
    asm volatile("cp.async.wait_group %0;" :: "n"(NN) : "memory");
}

__device__ __forceinline__ uint32_t packh2(float a, float b) {
    __half2 t = __floats2half2_rn(a, b);
    return *reinterpret_cast<uint32_t*>(&t);
}

// ---------------------------------------------------------------------------
// CSR build
// ---------------------------------------------------------------------------
__global__ void zero_int_kernel(int* __restrict__ a, int* __restrict__ b, int n) {
    int i = blockIdx.x * blockDim.x + threadIdx.x;
    if (i < n) { a[i] = 0; b[i] = 0; }
}

__global__ void degi_kernel(const int* __restrict__ dst, int* __restrict__ deg, int E) {
    int e = blockIdx.x * blockDim.x + threadIdx.x;
    if (e < E) atomicAdd(&deg[dst[e]], 1);
}

__global__ void scan1_kernel(const int* __restrict__ deg, int* __restrict__ rowptr,
                             int* __restrict__ bsum, int n) {
    __shared__ int warp_tot[8];
    int t = threadIdx.x, lane = t & 31, wid = t >> 5;
    int base = blockIdx.x * 1024 + t * 4;
    int v0 = (base + 0 < n) ? deg[base + 0] : 0;
    int v1 = (base + 1 < n) ? deg[base + 1] : 0;
    int v2 = (base + 2 < n) ? deg[base + 2] : 0;
    int v3 = (base + 3 < n) ? deg[base + 3] : 0;
    int tot = v0 + v1 + v2 + v3;

    int inc = tot;
#pragma unroll
    for (int off = 1; off < 32; off <<= 1) {
        int y = __shfl_up_sync(0xFFFFFFFF, inc, off);
        if (lane >= off) inc += y;
    }
    if (lane == 31) warp_tot[wid] = inc;
    __syncthreads();
    if (wid == 0) {
        int w = (lane < 8) ? warp_tot[lane] : 0;
        int wi = w;
#pragma unroll
        for (int off = 1; off < 8; off <<= 1) {
            int y = __shfl_up_sync(0xFFFFFFFF, wi, off);
            if (lane >= off) wi += y;
        }
        if (lane < 8) warp_tot[lane] = wi - w;
    }
    __syncthreads();
    int excl = warp_tot[wid] + inc - tot;

    if (base + 0 < n) rowptr[base + 0] = excl;
    if (base + 1 < n) rowptr[base + 1] = excl + v0;
    if (base + 2 < n) rowptr[base + 2] = excl + v0 + v1;
    if (base + 3 < n) rowptr[base + 3] = excl + v0 + v1 + v2;
    if (t == 255) bsum[blockIdx.x] = warp_tot[7] + inc;
}

__global__ void scan2_kernel(int* __restrict__ bsum, int nblk) {
    __shared__ int sh[1024];
    int t = threadIdx.x;
#pragma unroll
    for (int i = 0; i < 4; ++i) {
        int idx = t + i * 256;
        sh[idx] = (idx < nblk) ? bsum[idx] : 0;
    }
    __syncthreads();
    for (int off = 1; off < 1024; off <<= 1) {
        int v[4];
#pragma unroll
        for (int i = 0; i < 4; ++i) {
            int idx = t + i * 256;
            v[i] = (idx >= off) ? sh[idx - off] : 0;
        }
        __syncthreads();
#pragma unroll
        for (int i = 0; i < 4; ++i) sh[t + i * 256] += v[i];
        __syncthreads();
    }
#pragma unroll
    for (int i = 0; i < 4; ++i) {
        int idx = t + i * 256;
        if (idx < nblk) bsum[idx] = (idx == 0) ? 0 : sh[idx - 1];
    }
}

__global__ void scan3_kernel(int* __restrict__ rowptr, const int* __restrict__ bsum,
                             int n, int E) {
    int i = blockIdx.x * blockDim.x + threadIdx.x;
    if (i < n) rowptr[i] += bsum[i >> 10];
    if (i == 0) rowptr[n] = E;
}

__global__ void fill_kernel(const int* __restrict__ src, const int* __restrict__ dst,
                            const int* __restrict__ rowptr, int* __restrict__ cursor,
                            int* __restrict__ csr, int E) {
    int e = blockIdx.x * blockDim.x + threadIdx.x;
    if (e >= E) return;
    int d = dst[e];
    int pos = rowptr[d] + atomicAdd(&cursor[d], 1);
    csr[pos] = src[e];
}

// ---------------------------------------------------------------------------
// Gather (fp16 in -> fp16 mean out). Warp per node, 8-edge unroll.
// ---------------------------------------------------------------------------
__global__ void __launch_bounds__(256)
gather_kernel(const uint2* __restrict__ h2, const int* __restrict__ rowptr,
              const int* __restrict__ csr, __half* __restrict__ G, int n) {
    int gw   = (blockIdx.x * blockDim.x + threadIdx.x) >> 5;
    int lane = threadIdx.x & 31;
    if (gw >= n) return;
    int s0 = rowptr[gw], s1 = rowptr[gw + 1];
    float ax = 0.f, ay = 0.f, az = 0.f, aw = 0.f;
    int j = s0;
    for (; j + 8 <= s1; j += 8) {
        int idx[8];
        uint2 u[8];
#pragma unroll
        for (int q = 0; q < 8; ++q) idx[q] = __ldg(&csr[j + q]);
#pragma unroll
        for (int q = 0; q < 8; ++q) u[q] = h2[(size_t)idx[q] * 32 + lane];
#pragma unroll
        for (int q = 0; q < 8; ++q) {
            float2 p0 = __half22float2(*reinterpret_cast<__half2*>(&u[q].x));
            float2 p1 = __half22float2(*reinterpret_cast<__half2*>(&u[q].y));
            ax += p0.x; ay += p0.y; az += p1.x; aw += p1.y;
        }
    }
    for (; j + 4 <= s1; j += 4) {
        int idx[4];
        uint2 u[4];
#pragma unroll
        for (int q = 0; q < 4; ++q) idx[q] = __ldg(&csr[j + q]);
#pragma unroll
        for (int q = 0; q < 4; ++q) u[q] = h2[(size_t)idx[q] * 32 + lane];
#pragma unroll
        for (int q = 0; q < 4; ++q) {
            float2 p0 = __half22float2(*reinterpret_cast<__half2*>(&u[q].x));
            float2 p1 = __half22float2(*reinterpret_cast<__half2*>(&u[q].y));
            ax += p0.x; ay += p0.y; az += p1.x; aw += p1.y;
        }
    }
    for (; j < s1; ++j) {
        int i0 = __ldg(&csr[j]);
        uint2 u = h2[(size_t)i0 * 32 + lane];
        float2 p0 = __half22float2(*reinterpret_cast<__half2*>(&u.x));
        float2 p1 = __half22float2(*reinterpret_cast<__half2*>(&u.y));
        ax += p0.x; ay += p0.y; az += p1.x; aw += p1.y;
    }
    float rd = 1.0f / fmaxf((float)(s1 - s0), 1.0f);
    uint2 ov = make_uint2(packh2(ax * rd, ay * rd), packh2(az * rd, aw * rd));
    *(uint2*)(G + (size_t)gw * HID + lane * 4) = ov;
}

// ---------------------------------------------------------------------------
// Weight prep, split in two:
//   wprep_in_kernel:   w_in only (critical path before input GEMM)
//   wprep_rest_kernel: wl1|wr1, wl2|wr2, w_out (side stream)
// Layout identical to R14: wt[g] = [BN rows, Ktot] fp16, K-major.
// ---------------------------------------------------------------------------
__global__ void wprep_in_kernel(const float* __restrict__ w_in,
                                __half* __restrict__ wt) {
    int i = blockIdx.x * blockDim.x + threadIdx.x;
    if (i >= 128 * 256) return;
    int n = i / 256, k = i % 256;
    wt[i] = __float2half_rn(w_in[(size_t)k * 128 + n]);
}

__global__ void wprep_rest_kernel(const float* __restrict__ wl1,
                                  const float* __restrict__ wr1,
                                  const float* __restrict__ wl2,
                                  const float* __restrict__ wr2,
                                  const float* __restrict__ wo,
                                  __half* __restrict__ wt) {
    int i = blockIdx.x * blockDim.x + threadIdx.x;
    const float *W0, *W1; int K0, Ktot, BNw, j; __half* o;
    const int WSTR = 128 * 256;
    if (i < 32768)       { j = i;         W0 = wl1; W1 = wr1;     K0 = 128; Ktot = 256; BNw = 128; o = wt + 1 * WSTR; }
    else if (i < 65536)  { j = i - 32768; W0 = wl2; W1 = wr2;     K0 = 128; Ktot = 256; BNw = 128; o = wt + 2 * WSTR; }
    else if (i < 73728)  { j = i - 65536; W0 = wo;  W1 = nullptr; K0 = 128; Ktot = 128; BNw = 64;  o = wt + 3 * WSTR; }
    else return;
    int n = j / Ktot, k = j % Ktot;
    float w = (k < K0) ? W0[(size_t)k * BNw + n] : W1[(size_t)(k - K0) * BNw + n];
    o[j] = __float2half_rn(w);
}

// ---------------------------------------------------------------------------
// Persistent fp16 HMMA GEMM (R14/R13 body). Full B resident in smem;
// CTA loops over row-blocks. A: 3-stage cp.async (fp16, dual A0/A1 at NC0)
// or 2-stage reg staging (fp32 X).
// ---------------------------------------------------------------------------
template<int BN, int NC, int NC0, bool RELU, bool AFF, bool F32A, bool OUTF32>
__global__ void __launch_bounds__(256, 2)
mma_gemm_kernel(const float* __restrict__ X, int sX,
                const __half* __restrict__ A0, int sA0,
                const __half* __restrict__ A1, int sA1,
                const __half* __restrict__ W,
                const float* __restrict__ bias,
                const float* __restrict__ gamma,
                const float* __restrict__ beta,
                float* __restrict__ C,
                __half* __restrict__ H, int Nrows, int nBlocksRow)
{
    constexpr int KTOT   = NC * 32;
    constexpr int WN     = BN / 2;
    constexpr int NT8    = WN / 8;
    constexpr int NT16   = WN / 16;
    constexpr int APITCH = 80;
    constexpr int ABYTES = 128 * APITCH;
    constexpr int BPITCH = KTOT * 2 + 16;
    constexpr int BOFF   = 3 * ABYTES;
    constexpr int K8     = KTOT / 8;

    extern __shared__ __align__(128) char smem[];
    const uint32_t sbase = smem_u32(smem);
    const uint32_t bbase = sbase + BOFF;

    const int tid  = threadIdx.x;
    const int wid  = tid >> 5;
    const int lane = tid & 31;
    const int wm   = wid & 3;
    const int wn   = wid >> 2;

    // load full B once
    for (int s = tid; s < BN * K8; s += 256) {
        int n = s / K8, k8 = s % K8;
        cp16(bbase + n * BPITCH + k8 * 16, W + (size_t)n * KTOT + k8 * 8);
    }
    cp_commit();

    const int cb = wn * WN + 2 * (lane & 3);
    float2 scv[NT8], shv[NT8];
#pragma unroll
    for (int nt = 0; nt < NT8; ++nt) {
        int col = cb + nt * 8;
        float s0, h0, s1, h1;
        if constexpr (AFF) {
            s0 = __ldg(&gamma[col])     * rsqrtf(1.0f + 1e-5f);
            s1 = __ldg(&gamma[col + 1]) * rsqrtf(1.0f + 1e-5f);
            h0 = s0 * __ldg(&bias[col])     + __ldg(&beta[col]);
            h1 = s1 * __ldg(&bias[col + 1]) + __ldg(&beta[col + 1]);
        } else {
            s0 = 1.0f; s1 = 1.0f;
            h0 = __ldg(&bias[col]);
            h1 = __ldg(&bias[col + 1]);
        }
        scv[nt] = make_float2(s0, s1);
        shv[nt] = make_float2(h0, h1);
    }

    float4 af[2][2];

    auto load_tileA_f32 = [&](int row0, int c) {
#pragma unroll
        for (int s = 0; s < 2; ++s) {
            int f = tid + s * 256;
            int r = f >> 2, seg = f & 3;
            float4 v0 = make_float4(0.f, 0.f, 0.f, 0.f), v1 = v0;
            int grow = row0 + r;
            if (grow < Nrows) {
                const float* p = X + (size_t)grow * sX + c * 32 + seg * 8;
                v0 = *(const float4*)p;
                v1 = *(const float4*)(p + 4);
            }
            af[s][0] = v0; af[s][1] = v1;
        }
    };

    auto store_tileA_f16 = [&](int buf) {
        char* sp = smem + buf * ABYTES;
#pragma unroll
        for (int s = 0; s < 2; ++s) {
            int f = tid + s * 256;
            int r = f >> 2, seg = f & 3;
            uint4 v;
            v.x = packh2(af[s][0].x, af[s][0].y);
            v.y = packh2(af[s][0].z, af[s][0].w);
            v.z = packh2(af[s][1].x, af[s][1].y);
            v.w = packh2(af[s][1].z, af[s][1].w);
            *(uint4*)(sp + r * APITCH + seg * 16) = v;
        }
    };

    auto loadA_async = [&](int row0, int c, int buf) {
        const __half* Ap; int stride, koff;
        if (c < NC0) { Ap = A0; stride = sA0; koff = c * 32; }
        else         { Ap = A1; stride = sA1; koff = (c - NC0) * 32; }
        const uint32_t abase = sbase + buf * ABYTES;
#pragma unroll
        for (int s = 0; s < 2; ++s) {
            int f = tid + s * 256;
            int r = f >> 2, seg = f & 3;
            int grow = row0 + r;
            bool ok = grow < Nrows;
            size_t g = (size_t)(ok ? grow : 0) * stride + koff + seg * 8;
            cp16z(abase + r * APITCH + seg * 16, Ap + g, ok);
        }
    };

    float acc[2][NT8][4];

    auto compute = [&](int buf, int c) {
        const uint32_t aA = sbase + buf * ABYTES;
#pragma unroll
        for (int ks = 0; ks < 2; ++ks) {
            uint32_t a[2][4];
#pragma unroll
            for (int mt = 0; mt < 2; ++mt) {
                uint32_t off = (uint32_t)((wm * 32 + mt * 16 + (lane & 15)) * APITCH
                                          + (ks * 16 + (lane >> 4) * 8) * 2);
                ldsm_x4(a[mt], aA + off);
            }
#pragma unroll
            for (int nt2 = 0; nt2 < NT16; ++nt2) {
                int n_idx = wn * WN + nt2 * 16 + (lane & 7) + ((lane >> 4) & 1) * 8;
                int kg    = c * 32 + ks * 16 + ((lane >> 3) & 1) * 8;
                uint32_t b[4];
                ldsm_x4(b, bbase + (uint32_t)(n_idx * BPITCH + kg * 2));
#pragma unroll
                for (int mt = 0; mt < 2; ++mt) {
                    mma_f16(acc[mt][nt2 * 2 + 0], a[mt], b + 0);
                    mma_f16(acc[mt][nt2 * 2 + 1], a[mt], b + 2);
                }
            }
        }
    };

    for (int rb = blockIdx.x; rb < nBlocksRow; rb += gridDim.x) {
        const int row0 = rb * 128;

#pragma unroll
        for (int mt = 0; mt < 2; ++mt)
#pragma unroll
            for (int nt = 0; nt < NT8; ++nt)
#pragma unroll
                for (int q = 0; q < 4; ++q) acc[mt][nt][q] = 0.0f;

        if constexpr (!F32A) {
            loadA_async(row0, 0, 0); cp_commit();
            loadA_async(row0, 1, 1); cp_commit();
#pragma unroll
            for (int c = 0; c < NC; ++c) {
                if (c == NC - 1) cp_wait<0>(); else cp_wait<1>();
                __syncthreads();
                compute(c % 3, c);
                if (c + 2 < NC) {
                    loadA_async(row0, c + 2, (c + 2) % 3);
                    cp_commit();
                }
            }
        } else {
            cp_wait<0>();
            load_tileA_f32(row0, 0);
            store_tileA_f16(0);
            __syncthreads();
#pragma unroll
            for (int c = 0; c < NC; ++c) {
                if (c + 1 < NC) load_tileA_f32(row0, c + 1);
                compute(c & 1, c);
                if (c + 1 < NC) store_tileA_f16((c + 1) & 1);
                __syncthreads();
            }
        }

        const int rbase = row0 + wm * 32 + (lane >> 2);
#pragma unroll
        for (int mt = 0; mt < 2; ++mt) {
#pragma unroll
            for (int h = 0; h < 2; ++h) {
                int row = rbase + mt * 16 + h * 8;
                if (row >= Nrows) continue;
#pragma unroll
                for (int nt = 0; nt < NT8; ++nt) {
                    float v0 = acc[mt][nt][h * 2 + 0] * scv[nt].x + shv[nt].x;
                    float v1 = acc[mt][nt][h * 2 + 1] * scv[nt].y + shv[nt].y;
                    if constexpr (RELU) { v0 = fmaxf(v0, 0.0f); v1 = fmaxf(v1, 0.0f); }
                    size_t base = (size_t)row * BN + cb + nt * 8;
                    if constexpr (OUTF32) {
                        *(float2*)(C + base) = make_float2(v0, v1);
                    } else {
                        *(uint32_t*)(H + base) = packh2(v0, v1);
                    }
                }
            }
        }
        __syncthreads();
    }
}

// ---------------------------------------------------------------------------
// Host launcher — R14 fork/join: CSR (+rest-of-weights) overlaps input GEMM.
// ---------------------------------------------------------------------------
extern "C" void kernel_launch(void* const* d_in, const int* in_sizes, int n_in,
                              void* d_out, int out_size)
{
    const float* x     = (const float*)d_in[0];
    const int*   eidx  = (const int*)  d_in[1];
    const float* w_in  = (const float*)d_in[2];
    const float* b_in  = (const float*)d_in[3];
    const float* w_l1  = (const float*)d_in[4];
    const float* b_l1  = (const float*)d_in[5];
    const float* w_r1  = (const float*)d_in[6];
    const float* g1    = (const float*)d_in[7];
    const float* be1   = (const float*)d_in[8];
    const float* w_l2  = (const float*)d_in[9];
    const float* b_l2  = (const float*)d_in[10];
    const float* w_r2  = (const float*)d_in[11];
    const float* g2    = (const float*)d_in[12];
    const float* be2   = (const float*)d_in[13];
    const float* w_out = (const float*)d_in[14];
    const float* b_out = (const float*)d_in[15];
    float* out = (float*)d_out;

    const int N = in_sizes[0] / 256;
    const int E = in_sizes[1] / 2;
    const int* src = eidx;
    const int* dst = eidx + E;

    __half *h16a, *h16b, *h16c, *g16, *wt;
    int *degi, *cursor, *rowptr, *csr, *bsum;
    cudaGetSymbolAddress((void**)&h16a,   g_h16a);
    cudaGetSymbolAddress((void**)&h16b,   g_h16b);
    cudaGetSymbolAddress((void**)&h16c,   g_h16c);
    cudaGetSymbolAddress((void**)&g16,    g_g16);
    cudaGetSymbolAddress((void**)&degi,   g_degi);
    cudaGetSymbolAddress((void**)&cursor, g_cursor);
    cudaGetSymbolAddress((void**)&rowptr, g_rowptr);
    cudaGetSymbolAddress((void**)&csr,    g_csr);
    cudaGetSymbolAddress((void**)&bsum,   g_bsum);
    cudaGetSymbolAddress((void**)&wt,     g_wt);
    const int WSTR = 128 * 256;

    const int nBlocks    = (N + 255) / 256;
    const int eBlocks    = (E + 255) / 256;
    const int rowBlocks  = (N + 127) / 128;
    const int gemmGrid   = 304;
    const int scanBlocks = (N + 1023) / 1024;
    const int gatherBlocks = (int)(((long long)N * 32 + 255) / 256);

    const int S256 = 3 * (128 * 80) + 128 * (256 * 2 + 16);   // 98304
    const int S64  = 3 * (128 * 80) + 64  * (128 * 2 + 16);   // 48128
    cudaFuncSetAttribute(mma_gemm_kernel<128, 8, 8, true,  false, true,  false>,
                         cudaFuncAttributeMaxDynamicSharedMemorySize, S256);
    cudaFuncSetAttribute(mma_gemm_kernel<128, 8, 4, true,  true,  false, false>,
                         cudaFuncAttributeMaxDynamicSharedMemorySize, S256);
    cudaFuncSetAttribute(mma_gemm_kernel<64,  4, 4, false, false, false, true >,
                         cudaFuncAttributeMaxDynamicSharedMemorySize, S64);

    // lazy side-stream + events (created on first, uncaptured call)
    static cudaStream_t s2 = nullptr;
    static cudaEvent_t  e1 = nullptr, e2 = nullptr;
    if (s2 == nullptr) {
        cudaStreamCreateWithFlags(&s2, cudaStreamNonBlocking);
        cudaEventCreateWithFlags(&e1, cudaEventDisableTiming);
        cudaEventCreateWithFlags(&e2, cudaEventDisableTiming);
    }

    // ---- fork: rest-of-weights + CSR chain on s2 ----
    cudaEventRecord(e1, 0);
    cudaStreamWaitEvent(s2, e1, 0);

    wprep_rest_kernel<<<(73728 + 255) / 256, 256, 0, s2>>>(w_l1, w_r1, w_l2,
                                                           w_r2, w_out, wt);
    zero_int_kernel<<<nBlocks, 256, 0, s2>>>(degi, cursor, N);
    degi_kernel<<<eBlocks, 256, 0, s2>>>(dst, degi, E);
    scan1_kernel<<<scanBlocks, 256, 0, s2>>>(degi, rowptr, bsum, N);
    scan2_kernel<<<1, 256, 0, s2>>>(bsum, scanBlocks);
    scan3_kernel<<<nBlocks, 256, 0, s2>>>(rowptr, bsum, N, E);
    fill_kernel<<<eBlocks, 256, 0, s2>>>(src, dst, rowptr, cursor, csr, E);
    cudaEventRecord(e2, s2);

    // main: w_in prep + input GEMM
    wprep_in_kernel<<<(32768 + 255) / 256, 256>>>(w_in, wt);
    mma_gemm_kernel<128, 8, 8, true, false, true, false>
        <<<gemmGrid, 256, S256>>>(
        x, 256, nullptr, 0, nullptr, 0, wt + 0 * WSTR,
        b_in, nullptr, nullptr, nullptr, h16a, N, rowBlocks);

    // ---- join ----
    cudaStreamWaitEvent(0, e2, 0);

    // SAGE layer 1
    gather_kernel<<<gatherBlocks, 256>>>((const uint2*)h16a, rowptr, csr, g16, N);
    mma_gemm_kernel<128, 8, 4, true, true, false, false>
        <<<gemmGrid, 256, S256>>>(
        nullptr, 0, g16, 128, h16a, 128, wt + 1 * WSTR,
        b_l1, g1, be1, nullptr, h16b, N, rowBlocks);

    // SAGE layer 2
    gather_kernel<<<gatherBlocks, 256>>>((const uint2*)h16b, rowptr, csr, g16, N);
    mma_gemm_kernel<128, 8, 4, true, true, false, false>
        <<<gemmGrid, 256, S256>>>(
        nullptr, 0, g16, 128, h16b, 128, wt + 2 * WSTR,
        b_l2, g2, be2, nullptr, h16c, N, rowBlocks);

    // output layer
    mma_gemm_kernel<64, 4, 4, false, false, false, true>
        <<<gemmGrid, 256, S64>>>(
        nullptr, 0, h16c, 128, nullptr, 0, wt + 3 * WSTR,
        b_out, nullptr, nullptr, out, nullptr, N, rowBlocks);
}